// round 10
// baseline (speedup 1.0000x reference)
#include <cuda_runtime.h>
#include <cuda_fp16.h>
#include <math.h>
#include <stdint.h>

// Problem constants
#define Bn   256
#define Nn   199
#define Fin  256
#define Hh   8
#define Fout 256
#define HF   2048          // Hh * Fout
#define BN   (Bn * Nn)     // 50944
#define MW   7             // mask words per row

// gemm1 (mma.sync) tiling — single-segment fp16: fp16(X) @ fp16(W)
#define KS   256
#define KCH  32            // K chunk per smem stage
#define NKC  (KS / KCH)    // 8
#define LDS  40            // gemm1 smem row stride (halfs): 80B, conflict-free
#define GSTG 4             // cp.async stages
#define G1_SMEM (2 * GSTG * 128 * LDS * 2)   // 81920 B

// attn (mma.sync) tiling — P fp16 exact-normalized, V fp16; d split across CTAs
#define NJP   208          // padded j (13*16)
#define NPR   104          // j pairs
#define LDPH  216          // P smem row stride (halfs): 432B -> conflict-free
#define LDV   136          // V smem row stride (halfs): 272B -> conflict-free ldsm_t
#define NSTEP 13           // 13 k16-steps (K = 208)
#define VSTG  4

// attn smem byte offsets (all 16B aligned)
#define OF_PH 0
#define OF_VS 55296        // 128*216*2
#define OF_UH 72704        // + 4*16*136*2
#define OF_SI 73120        // + 208*2
#define OF_RED 73632
#define OF_MB 73760
#define ATTN_SMEM 79360    // 73760 + 199*7*4 = 79332, rounded to 16

// chunked producer/consumer interleave (feats stays L2-resident)
#define NCHK   4
#define TPC    100         // gemm m-tiles per chunk (last = 98)
#define BHPC   512         // bh per chunk (64 batches)

// ---------------------------------------------------------------------------
// Scratch (device globals — no runtime allocation allowed)
// ---------------------------------------------------------------------------
__device__ __half        g_fhi[(size_t)BN * HF];         // feats fp16 (209 MB)
__device__ float         g_eneigh[(size_t)Bn * Hh * Nn];
__device__ float         g_wneigh[Hh * Fin];
__device__ unsigned      g_mbits[Nn * MW];
__device__ __half        g_Xs[(size_t)BN * KS];          // fp16(X) (26 MB)
__device__ __half        g_Wt[(size_t)HF * KS];          // fp16(W^T) (1 MB)

// ---------------------------------------------------------------------------
// mma.sync / ldmatrix / cp.async helpers (sm_80+, valid on plain sm_100)
// ---------------------------------------------------------------------------
__device__ __forceinline__ void ldsm4(uint32_t& r0, uint32_t& r1, uint32_t& r2,
                                      uint32_t& r3, const void* p) {
    uint32_t a = (uint32_t)__cvta_generic_to_shared(p);
    asm volatile("ldmatrix.sync.aligned.m8n8.x4.shared.b16 {%0,%1,%2,%3}, [%4];"
                 : "=r"(r0), "=r"(r1), "=r"(r2), "=r"(r3) : "r"(a));
}
__device__ __forceinline__ void ldsm4t(uint32_t& r0, uint32_t& r1, uint32_t& r2,
                                       uint32_t& r3, const void* p) {
    uint32_t a = (uint32_t)__cvta_generic_to_shared(p);
    asm volatile("ldmatrix.sync.aligned.m8n8.x4.trans.shared.b16 {%0,%1,%2,%3}, [%4];"
                 : "=r"(r0), "=r"(r1), "=r"(r2), "=r"(r3) : "r"(a));
}
__device__ __forceinline__ void mma_f16(float* c, const uint32_t* a,
                                        uint32_t b0, uint32_t b1) {
    asm volatile(
        "mma.sync.aligned.m16n8k16.row.col.f32.f16.f16.f32 "
        "{%0,%1,%2,%3}, {%4,%5,%6,%7}, {%8,%9}, {%0,%1,%2,%3};"
        : "+f"(c[0]), "+f"(c[1]), "+f"(c[2]), "+f"(c[3])
        : "r"(a[0]), "r"(a[1]), "r"(a[2]), "r"(a[3]), "r"(b0), "r"(b1));
}
__device__ __forceinline__ void cp16(void* s, const void* g) {
    uint32_t sa = (uint32_t)__cvta_generic_to_shared(s);
    asm volatile("cp.async.cg.shared.global [%0], [%1], 16;" :: "r"(sa), "l"(g));
}
__device__ __forceinline__ void cp16z(void* s, const void* g, int sz) {
    uint32_t sa = (uint32_t)__cvta_generic_to_shared(s);
    asm volatile("cp.async.cg.shared.global [%0], [%1], 16, %2;"
                 :: "r"(sa), "l"(g), "r"(sz));
}
#define CP_COMMIT() asm volatile("cp.async.commit_group;" ::: "memory")
#define CP_WAIT2()  asm volatile("cp.async.wait_group 2;" ::: "memory")

// ---------------------------------------------------------------------------
// Kernel P0: w_neigh + adjacency bitmask
// ---------------------------------------------------------------------------
__global__ void prep_kernel(const float* __restrict__ W,
                            const float* __restrict__ a_neigh,
                            const int*   __restrict__ A) {
    int t = blockIdx.x * blockDim.x + threadIdx.x;
    int stride = gridDim.x * blockDim.x;
    for (int idx = t; idx < Hh * Fin; idx += stride) {
        int h = idx / Fin, f = idx % Fin;
        const float* wp = W + ((size_t)h * Fin + f) * Fout;
        const float* ap = a_neigh + h * Fout;
        float s = 0.f;
        for (int d = 0; d < Fout; d++) s += wp[d] * ap[d];
        g_wneigh[idx] = s;
    }
    for (int idx = t; idx < Nn * MW; idx += stride) {
        int i = idx / MW, c = idx % MW;
        unsigned m = 0u;
        for (int bb = 0; bb < 32; bb++) {
            int j = c * 32 + bb;
            if (j < Nn && A[i * Nn + j] != 0) m |= (1u << bb);
        }
        g_mbits[idx] = m;
    }
}

// ---------------------------------------------------------------------------
// Kernel P1: e_neigh[b,h,n] = X[b,n,:] . w_neigh[h,:]  (fp32 exact, feeds exp)
// Fused: also writes fp16(X) to g_Xs (row already in registers).
// ---------------------------------------------------------------------------
__global__ void __launch_bounds__(256) eneigh_kernel(const float* __restrict__ X) {
    __shared__ float ws[Hh * Fin];
    const int tid = threadIdx.x;
    for (int i = tid; i < Hh * Fin; i += 256) ws[i] = g_wneigh[i];
    __syncthreads();

    const int warp = tid >> 5, lane = tid & 31;
    const int row = blockIdx.x * 8 + warp;
    const float* xp = X + (size_t)row * Fin;
    float x[8];
    #pragma unroll
    for (int k = 0; k < 8; k++) x[k] = xp[lane + 32 * k];

    // fp16 copy of X (coalesced 64B segments per k)
    #pragma unroll
    for (int k = 0; k < 8; k++)
        g_Xs[(size_t)row * KS + lane + 32 * k] = __float2half_rn(x[k]);

    const int b = row / Nn, n = row % Nn;
    #pragma unroll
    for (int h = 0; h < Hh; h++) {
        float s = 0.f;
        #pragma unroll
        for (int k = 0; k < 8; k++) s = fmaf(x[k], ws[h * Fin + lane + 32 * k], s);
        #pragma unroll
        for (int o = 16; o > 0; o >>= 1) s += __shfl_xor_sync(0xffffffffu, s, o);
        if (lane == 0) g_eneigh[(size_t)(b * Hh + h) * Nn + n] = s;
    }
}

// ---------------------------------------------------------------------------
// Kernel S1: W^T -> fp16: g_Wt[col][f] = fp16(W[h][f][d]), col = h*256+d
// ---------------------------------------------------------------------------
__global__ void __launch_bounds__(256) split_w_kernel(const float* __restrict__ W) {
    const int idx = blockIdx.x * 256 + threadIdx.x;   // < HF*64
    const int col = idx >> 6, f4 = idx & 63;
    const int h = col >> 8, d = col & 255;
    #pragma unroll
    for (int i = 0; i < 4; i++) {
        int f = f4 * 4 + i;
        float v = W[((size_t)h * Fin + f) * Fout + d];
        g_Wt[(size_t)col * KS + f] = __float2half_rn(v);
    }
}

// ---------------------------------------------------------------------------
// Kernel G1 (mma.sync + cp.async 4-stage): feats = fp16(X) @ fp16(W'), K=256.
// tb = m-tile base for chunked launch. Grid x = 16 n-tiles (A-tile L2 reuse).
// ---------------------------------------------------------------------------
__global__ void __launch_bounds__(256, 2) gemm1_mma(int tb) {
    extern __shared__ char gsm[];
    __half* As = (__half*)gsm;                              // [GSTG*128][LDS]
    __half* Bs = (__half*)(gsm + (size_t)GSTG * 128 * LDS * 2);

    const int tid  = threadIdx.x;
    const int lane = tid & 31, warp = tid >> 5;
    const int wm = warp >> 2, wn = warp & 3;          // warp grid 2x4
    const int m0 = (tb + blockIdx.y) * 128, n0 = blockIdx.x * 128;

    const __half* Ag = g_Xs + (size_t)m0 * KS;
    const __half* Bg = g_Wt + (size_t)n0 * KS;

    const int lrow0 = tid >> 2, lc16 = tid & 3;
    const int lrow1 = (tid + 256) >> 2;

    #define G1_ISSUE(c) do {                                                     \
        const int _st = (c) & 3, _ko = (c) * KCH;                                \
        cp16(As + (size_t)(_st * 128 + lrow0) * LDS + lc16 * 8,                  \
             Ag + (size_t)lrow0 * KS + _ko + lc16 * 8);                          \
        cp16(As + (size_t)(_st * 128 + lrow1) * LDS + lc16 * 8,                  \
             Ag + (size_t)lrow1 * KS + _ko + lc16 * 8);                          \
        cp16(Bs + (size_t)(_st * 128 + lrow0) * LDS + lc16 * 8,                  \
             Bg + (size_t)lrow0 * KS + _ko + lc16 * 8);                          \
        cp16(Bs + (size_t)(_st * 128 + lrow1) * LDS + lc16 * 8,                  \
             Bg + (size_t)lrow1 * KS + _ko + lc16 * 8);                          \
    } while (0)

    G1_ISSUE(0); CP_COMMIT();
    G1_ISSUE(1); CP_COMMIT();
    G1_ISSUE(2); CP_COMMIT();

    float acc[4][4][4];
    #pragma unroll
    for (int i = 0; i < 4; i++)
        #pragma unroll
        for (int j = 0; j < 4; j++)
            #pragma unroll
            for (int q = 0; q < 4; q++) acc[i][j][q] = 0.f;

    for (int c = 0; c < NKC; c++) {
        CP_WAIT2();
        __syncthreads();
        if (c + 3 < NKC) G1_ISSUE(c + 3);
        CP_COMMIT();

        const int sb = (c & 3) * 128;
        #pragma unroll
        for (int ks = 0; ks < 2; ks++) {
            uint32_t ra[4][4], rb[2][4];
            #pragma unroll
            for (int am = 0; am < 4; am++)
                ldsm4(ra[am][0], ra[am][1], ra[am][2], ra[am][3],
                      As + (size_t)(sb + wm * 64 + am * 16 + (lane & 15)) * LDS
                         + ks * 16 + (lane >> 4) * 8);
            #pragma unroll
            for (int bn = 0; bn < 2; bn++)
                ldsm4(rb[bn][0], rb[bn][1], rb[bn][2], rb[bn][3],
                      Bs + (size_t)(sb + wn * 32 + bn * 16 + (lane & 7)
                                    + ((lane >> 4) << 3)) * LDS
                         + ks * 16 + ((lane >> 3) & 1) * 8);
            #pragma unroll
            for (int am = 0; am < 4; am++)
                #pragma unroll
                for (int an = 0; an < 4; an++)
                    mma_f16(acc[am][an], ra[am],
                            rb[an >> 1][(an & 1) * 2], rb[an >> 1][(an & 1) * 2 + 1]);
        }
    }

    // epilogue: fp32 -> fp16 feats
    #pragma unroll
    for (int am = 0; am < 4; am++) {
        const int row = m0 + wm * 64 + am * 16 + (lane >> 2);
        #pragma unroll
        for (int an = 0; an < 4; an++) {
            const int col = n0 + wn * 32 + an * 8 + (lane & 3) * 2;
            #pragma unroll
            for (int rr = 0; rr < 2; rr++) {
                const size_t off = (size_t)(row + rr * 8) * HF + col;
                *(__half2*)(g_fhi + off) =
                    __floats2half2_rn(acc[am][an][rr * 2], acc[am][an][rr * 2 + 1]);
            }
        }
    }
}

// ---------------------------------------------------------------------------
// Kernel A2 (mma.sync + cp.async): masked softmax + P@V, d-SPLIT for 2 CTA/SM.
// blockIdx.x: bit0 = d-half, bit1 = i-tile. Each CTA: M=128 x N=128, K=208.
// P = fp16(u_j) exact-normalized; V = fp16 feats, single segment.
// ---------------------------------------------------------------------------
__global__ void __launch_bounds__(256, 2) attn_mma(const float* __restrict__ bias,
                                                   float* __restrict__ out,
                                                   int bh_base) {
    extern __shared__ char sm[];
    __half*   Ph   = (__half*)(sm + OF_PH);     // [128][LDPH]
    __half*   Vs   = (__half*)(sm + OF_VS);     // [VSTG][16][LDV]
    __half*   uh   = (__half*)(sm + OF_UH);     // [NJP]
    float*    Sinv = (float*)(sm + OF_SI);      // [128]
    float*    red  = (float*)(sm + OF_RED);     // [32]
    unsigned* mb   = (unsigned*)(sm + OF_MB);   // [Nn*MW]

    const int tid = threadIdx.x, lane = tid & 31, warp = tid >> 5;
    const int bh = bh_base + blockIdx.y, b = bh >> 3, h = bh & 7;
    const int dh = blockIdx.x & 1;              // d-half: cols [dh*128, dh*128+128)
    const int i0 = (blockIdx.x >> 1) * 128;     // i-tile
    const int wm = warp >> 2, wn = warp & 3;    // warp grid 2x4 (64i x 32d)

    const __half* fbh = g_fhi + (size_t)b * Nn * HF + h * Fout + dh * 128;

    // V stage loader: one cp16 per thread (16 rows x 128 halfs = 4096 B)
    #define AT_ISSUE(stp) do {                                                   \
        const int _st = (stp) & 3;                                               \
        const int _row = tid >> 4, _c16 = tid & 15;                              \
        const int _j = (stp) * 16 + _row;                                        \
        const int _sz = (_j < Nn) ? 16 : 0;                                      \
        const __half* _g = fbh + (size_t)(_j < Nn ? _j : 0) * HF + _c16 * 8;     \
        cp16z(Vs + (size_t)(_st * 16 + _row) * LDV + _c16 * 8, _g, _sz);         \
    } while (0)

    // prologue V loads overlap softmax/P-build below
    AT_ISSUE(0); CP_COMMIT();
    AT_ISSUE(1); CP_COMMIT();
    AT_ISSUE(2); CP_COMMIT();

    for (int i = tid; i < Nn * MW; i += 256) mb[i] = g_mbits[i];

    // softmax weights: u_j = exp(e_j - gmax), quantized to fp16
    const float* ep = g_eneigh + (size_t)bh * Nn;
    float e = (tid < Nn) ? ep[tid] : -1e30f;
    float m = e;
    #pragma unroll
    for (int o = 16; o > 0; o >>= 1) m = fmaxf(m, __shfl_xor_sync(0xffffffffu, m, o));
    if (lane == 0) red[warp] = m;
    __syncthreads();
    if (tid == 0) {
        float mm = red[0];
        for (int w = 1; w < 8; w++) mm = fmaxf(mm, red[w]);
        red[0] = mm;
    }
    __syncthreads();
    const float gmax = red[0];
    if (tid < NJP)
        uh[tid] = (tid < Nn) ? __float2half_rn(__expf(e - gmax)) : __half(0.f);
    __syncthreads();

    // build P tile (fp16, masked) + row sums from the SAME quantized values
    for (int t = tid; t < 128 * NPR; t += 256) {
        const int i = t / NPR, jp = t - i * NPR;
        const int ig = i0 + i;
        uint32_t mw_ = 0u;
        if (ig < Nn) {
            const unsigned* mrow = mb + ig * MW;
            const int j0 = jp * 2, j1 = j0 + 1;
            if ((mrow[j0 >> 5] >> (j0 & 31)) & 1u) mw_ |= 0x0000FFFFu;
            if ((mrow[j1 >> 5] >> (j1 & 31)) & 1u) mw_ |= 0xFFFF0000u;
        }
        const uint32_t uhp = ((const uint32_t*)uh)[jp];
        ((uint32_t*)(Ph + (size_t)i * LDPH))[jp] = uhp & mw_;
    }
    for (int il = warp; il < 128; il += 8) {
        const int ig = i0 + il;
        float s = 0.f;
        if (ig < Nn) {
            const unsigned* mrow = mb + ig * MW;
            for (int j = lane; j < Nn; j += 32)
                if (mrow[j >> 5] & (1u << (j & 31))) s += __half2float(uh[j]);
        }
        #pragma unroll
        for (int o = 16; o > 0; o >>= 1) s += __shfl_xor_sync(0xffffffffu, s, o);
        if (lane == 0) Sinv[il] = (ig < Nn) ? (1.f / s) : 0.f;
    }
    __syncthreads();

    // K-loop: 13 steps of k=16, 4-stage cp.async
    float acc[4][4][4];
    #pragma unroll
    for (int i = 0; i < 4; i++)
        #pragma unroll
        for (int j = 0; j < 4; j++)
            #pragma unroll
            for (int q = 0; q < 4; q++) acc[i][j][q] = 0.f;

    for (int step = 0; step < NSTEP; step++) {
        CP_WAIT2();
        __syncthreads();
        if (step + 3 < NSTEP) AT_ISSUE(step + 3);
        CP_COMMIT();

        const int kc = step * 16;
        const int vb = (step & 3) * 16;

        uint32_t ra[4][4], rb[2][4];
        #pragma unroll
        for (int am = 0; am < 4; am++)
            ldsm4(ra[am][0], ra[am][1], ra[am][2], ra[am][3],
                  Ph + (size_t)(wm * 64 + am * 16 + (lane & 15)) * LDPH
                     + kc + (lane >> 4) * 8);
        #pragma unroll
        for (int q = 0; q < 2; q++)
            ldsm4t(rb[q][0], rb[q][1], rb[q][2], rb[q][3],
                   Vs + (size_t)(vb + (lane & 15)) * LDV
                      + wn * 32 + q * 16 + ((lane >> 4) << 3));
        #pragma unroll
        for (int am = 0; am < 4; am++)
            #pragma unroll
            for (int an = 0; an < 4; an++)
                mma_f16(acc[am][an], ra[am],
                        rb[an >> 1][(an & 1) * 2], rb[an >> 1][(an & 1) * 2 + 1]);
    }

    // epilogue: scale by Sinv, add bias, store fp32
    #pragma unroll
    for (int am = 0; am < 4; am++) {
        const int il = wm * 64 + am * 16 + (lane >> 2);
        const int ig0 = i0 + il, ig1 = ig0 + 8;
        const float si0 = Sinv[il], si1 = Sinv[il + 8];
        #pragma unroll
        for (int an = 0; an < 4; an++) {
            const int d = dh * 128 + wn * 32 + an * 8 + (lane & 3) * 2;
            const float bv0 = bias[h * Fout + d];
            const float bv1 = bias[h * Fout + d + 1];
            if (ig0 < Nn) {
                float* p = out + (size_t)(b * Nn + ig0) * HF + h * Fout + d;
                *(float2*)p = make_float2(fmaf(acc[am][an][0], si0, bv0),
                                          fmaf(acc[am][an][1], si0, bv1));
            }
            if (ig1 < Nn) {
                float* p = out + (size_t)(b * Nn + ig1) * HF + h * Fout + d;
                *(float2*)p = make_float2(fmaf(acc[am][an][2], si1, bv0),
                                          fmaf(acc[am][an][3], si1, bv1));
            }
        }
    }
}

// ---------------------------------------------------------------------------
extern "C" void kernel_launch(void* const* d_in, const int* in_sizes, int n_in,
                              void* d_out, int out_size) {
    const float* X       = (const float*)d_in[0];
    const int*   A       = (const int*)  d_in[1];
    const float* W       = (const float*)d_in[2];
    // d_in[3] = a_self: no effect on output (softmax row-constant cancels)
    const float* a_neigh = (const float*)d_in[4];
    const float* bias    = (const float*)d_in[5];
    float* out = (float*)d_out;

    prep_kernel<<<64, 256>>>(W, a_neigh, A);
    eneigh_kernel<<<BN / 8, 256>>>(X);        // also writes fp16(X)
    split_w_kernel<<<HF * 64 / 256, 256>>>(W);

    cudaFuncSetAttribute(gemm1_mma, cudaFuncAttributeMaxDynamicSharedMemorySize,
                         G1_SMEM);
    cudaFuncSetAttribute(attn_mma, cudaFuncAttributeMaxDynamicSharedMemorySize,
                         ATTN_SMEM);

    // chunked interleave: gemm chunk k writes feats rows that attn chunk k
    // reads while still L2-resident (stream order serializes them).
    for (int k = 0; k < NCHK; k++) {
        const int tb = k * TPC;
        const int nt = (k == NCHK - 1) ? (BN / 128 - tb) : TPC;   // 100,100,100,98
        gemm1_mma<<<dim3(HF / 128, nt), 256, G1_SMEM>>>(tb);
        attn_mma<<<dim3(4, BHPC), 256, ATTN_SMEM>>>(bias, out, k * BHPC);
    }
}

// round 11
// speedup vs baseline: 1.0473x; 1.0473x over previous
#include <cuda_runtime.h>
#include <cuda_fp16.h>
#include <math.h>
#include <stdint.h>

// Problem constants
#define Bn   256
#define Nn   199
#define Fin  256
#define Hh   8
#define Fout 256
#define HF   2048          // Hh * Fout
#define BN   (Bn * Nn)     // 50944
#define MW   7             // mask words per row

// gemm1 (mma.sync) tiling — single-segment fp16: fp16(X) @ fp16(W)
#define KS   256
#define KCH  32            // K chunk per smem stage
#define NKC  (KS / KCH)    // 8
#define LDS  40            // gemm1 smem row stride (halfs): 80B, conflict-free
#define GSTG 4             // cp.async stages
#define G1_SMEM (2 * GSTG * 128 * LDS * 2)   // 81920 B

// attn (mma.sync) tiling — P fp16 exact-normalized, V fp16; d split across CTAs
#define NJP   208          // padded j (13*16)
#define NPR   104          // j pairs
#define LDPH  216          // P smem row stride (halfs): 432B -> conflict-free
#define LDV   136          // V smem row stride (halfs): 272B -> conflict-free ldsm_t
#define NSTEP 13           // 13 k16-steps (K = 208)
#define VSTG  4

// attn smem byte offsets (all 16B aligned)
#define OF_PH 0
#define OF_VS 55296        // 128*216*2
#define OF_UH 72704        // + 4*16*136*2
#define OF_SI 73120        // + 208*2
#define OF_RED 73632
#define OF_MB 73760
#define ATTN_SMEM 79360    // 73760 + 199*7*4 = 79332, rounded to 16

// ---------------------------------------------------------------------------
// Scratch (device globals — no runtime allocation allowed)
// ---------------------------------------------------------------------------
__device__ __half        g_fhi[(size_t)BN * HF];         // feats fp16 (209 MB)
__device__ float         g_eneigh[(size_t)Bn * Hh * Nn];
__device__ float         g_wneigh[Hh * Fin];
__device__ unsigned      g_mbits[Nn * MW];
__device__ __half        g_Xs[(size_t)BN * KS];          // fp16(X) (26 MB)
__device__ __half        g_Wt[(size_t)HF * KS];          // fp16(W^T) (1 MB)

// ---------------------------------------------------------------------------
// mma.sync / ldmatrix / cp.async helpers (sm_80+, valid on plain sm_100)
// ---------------------------------------------------------------------------
__device__ __forceinline__ void ldsm4(uint32_t& r0, uint32_t& r1, uint32_t& r2,
                                      uint32_t& r3, const void* p) {
    uint32_t a = (uint32_t)__cvta_generic_to_shared(p);
    asm volatile("ldmatrix.sync.aligned.m8n8.x4.shared.b16 {%0,%1,%2,%3}, [%4];"
                 : "=r"(r0), "=r"(r1), "=r"(r2), "=r"(r3) : "r"(a));
}
__device__ __forceinline__ void ldsm4t(uint32_t& r0, uint32_t& r1, uint32_t& r2,
                                       uint32_t& r3, const void* p) {
    uint32_t a = (uint32_t)__cvta_generic_to_shared(p);
    asm volatile("ldmatrix.sync.aligned.m8n8.x4.trans.shared.b16 {%0,%1,%2,%3}, [%4];"
                 : "=r"(r0), "=r"(r1), "=r"(r2), "=r"(r3) : "r"(a));
}
__device__ __forceinline__ void mma_f16(float* c, const uint32_t* a,
                                        uint32_t b0, uint32_t b1) {
    asm volatile(
        "mma.sync.aligned.m16n8k16.row.col.f32.f16.f16.f32 "
        "{%0,%1,%2,%3}, {%4,%5,%6,%7}, {%8,%9}, {%0,%1,%2,%3};"
        : "+f"(c[0]), "+f"(c[1]), "+f"(c[2]), "+f"(c[3])
        : "r"(a[0]), "r"(a[1]), "r"(a[2]), "r"(a[3]), "r"(b0), "r"(b1));
}
__device__ __forceinline__ void cp16(void* s, const void* g) {
    uint32_t sa = (uint32_t)__cvta_generic_to_shared(s);
    asm volatile("cp.async.cg.shared.global [%0], [%1], 16;" :: "r"(sa), "l"(g));
}
__device__ __forceinline__ void cp16z(void* s, const void* g, int sz) {
    uint32_t sa = (uint32_t)__cvta_generic_to_shared(s);
    asm volatile("cp.async.cg.shared.global [%0], [%1], 16, %2;"
                 :: "r"(sa), "l"(g), "r"(sz));
}
#define CP_COMMIT() asm volatile("cp.async.commit_group;" ::: "memory")
#define CP_WAIT2()  asm volatile("cp.async.wait_group 2;" ::: "memory")

// ---------------------------------------------------------------------------
// Kernel P0: w_neigh + adjacency bitmask
// ---------------------------------------------------------------------------
__global__ void prep_kernel(const float* __restrict__ W,
                            const float* __restrict__ a_neigh,
                            const int*   __restrict__ A) {
    int t = blockIdx.x * blockDim.x + threadIdx.x;
    int stride = gridDim.x * blockDim.x;
    for (int idx = t; idx < Hh * Fin; idx += stride) {
        int h = idx / Fin, f = idx % Fin;
        const float* wp = W + ((size_t)h * Fin + f) * Fout;
        const float* ap = a_neigh + h * Fout;
        float s = 0.f;
        for (int d = 0; d < Fout; d++) s += wp[d] * ap[d];
        g_wneigh[idx] = s;
    }
    for (int idx = t; idx < Nn * MW; idx += stride) {
        int i = idx / MW, c = idx % MW;
        unsigned m = 0u;
        for (int bb = 0; bb < 32; bb++) {
            int j = c * 32 + bb;
            if (j < Nn && A[i * Nn + j] != 0) m |= (1u << bb);
        }
        g_mbits[idx] = m;
    }
}

// ---------------------------------------------------------------------------
// Kernel P1: e_neigh[b,h,n] = X[b,n,:] . w_neigh[h,:]  (fp32 exact, feeds exp)
// Fused: also writes fp16(X) to g_Xs (row already in registers).
// ---------------------------------------------------------------------------
__global__ void __launch_bounds__(256) eneigh_kernel(const float* __restrict__ X) {
    __shared__ float ws[Hh * Fin];
    const int tid = threadIdx.x;
    for (int i = tid; i < Hh * Fin; i += 256) ws[i] = g_wneigh[i];
    __syncthreads();

    const int warp = tid >> 5, lane = tid & 31;
    const int row = blockIdx.x * 8 + warp;
    const float* xp = X + (size_t)row * Fin;
    float x[8];
    #pragma unroll
    for (int k = 0; k < 8; k++) x[k] = xp[lane + 32 * k];

    // fp16 copy of X (coalesced 64B segments per k)
    #pragma unroll
    for (int k = 0; k < 8; k++)
        g_Xs[(size_t)row * KS + lane + 32 * k] = __float2half_rn(x[k]);

    const int b = row / Nn, n = row % Nn;
    #pragma unroll
    for (int h = 0; h < Hh; h++) {
        float s = 0.f;
        #pragma unroll
        for (int k = 0; k < 8; k++) s = fmaf(x[k], ws[h * Fin + lane + 32 * k], s);
        #pragma unroll
        for (int o = 16; o > 0; o >>= 1) s += __shfl_xor_sync(0xffffffffu, s, o);
        if (lane == 0) g_eneigh[(size_t)(b * Hh + h) * Nn + n] = s;
    }
}

// ---------------------------------------------------------------------------
// Kernel S1: W^T -> fp16: g_Wt[col][f] = fp16(W[h][f][d]), col = h*256+d
// ---------------------------------------------------------------------------
__global__ void __launch_bounds__(256) split_w_kernel(const float* __restrict__ W) {
    const int idx = blockIdx.x * 256 + threadIdx.x;   // < HF*64
    const int col = idx >> 6, f4 = idx & 63;
    const int h = col >> 8, d = col & 255;
    #pragma unroll
    for (int i = 0; i < 4; i++) {
        int f = f4 * 4 + i;
        float v = W[((size_t)h * Fin + f) * Fout + d];
        g_Wt[(size_t)col * KS + f] = __float2half_rn(v);
    }
}

// ---------------------------------------------------------------------------
// Kernel G1 (mma.sync + cp.async 4-stage): feats = fp16(X) @ fp16(W'), K=256.
// Grid: (16 n-tiles, 398 m-tiles) — consecutive CTAs share the A tile in L2.
// ---------------------------------------------------------------------------
__global__ void __launch_bounds__(256, 2) gemm1_mma() {
    extern __shared__ char gsm[];
    __half* As = (__half*)gsm;                              // [GSTG*128][LDS]
    __half* Bs = (__half*)(gsm + (size_t)GSTG * 128 * LDS * 2);

    const int tid  = threadIdx.x;
    const int lane = tid & 31, warp = tid >> 5;
    const int wm = warp >> 2, wn = warp & 3;          // warp grid 2x4
    const int m0 = blockIdx.y * 128, n0 = blockIdx.x * 128;

    const __half* Ag = g_Xs + (size_t)m0 * KS;
    const __half* Bg = g_Wt + (size_t)n0 * KS;

    const int lrow0 = tid >> 2, lc16 = tid & 3;
    const int lrow1 = (tid + 256) >> 2;

    #define G1_ISSUE(c) do {                                                     \
        const int _st = (c) & 3, _ko = (c) * KCH;                                \
        cp16(As + (size_t)(_st * 128 + lrow0) * LDS + lc16 * 8,                  \
             Ag + (size_t)lrow0 * KS + _ko + lc16 * 8);                          \
        cp16(As + (size_t)(_st * 128 + lrow1) * LDS + lc16 * 8,                  \
             Ag + (size_t)lrow1 * KS + _ko + lc16 * 8);                          \
        cp16(Bs + (size_t)(_st * 128 + lrow0) * LDS + lc16 * 8,                  \
             Bg + (size_t)lrow0 * KS + _ko + lc16 * 8);                          \
        cp16(Bs + (size_t)(_st * 128 + lrow1) * LDS + lc16 * 8,                  \
             Bg + (size_t)lrow1 * KS + _ko + lc16 * 8);                          \
    } while (0)

    G1_ISSUE(0); CP_COMMIT();
    G1_ISSUE(1); CP_COMMIT();
    G1_ISSUE(2); CP_COMMIT();

    float acc[4][4][4];
    #pragma unroll
    for (int i = 0; i < 4; i++)
        #pragma unroll
        for (int j = 0; j < 4; j++)
            #pragma unroll
            for (int q = 0; q < 4; q++) acc[i][j][q] = 0.f;

    for (int c = 0; c < NKC; c++) {
        CP_WAIT2();
        __syncthreads();
        if (c + 3 < NKC) G1_ISSUE(c + 3);
        CP_COMMIT();

        const int sb = (c & 3) * 128;
        #pragma unroll
        for (int ks = 0; ks < 2; ks++) {
            uint32_t ra[4][4], rb[2][4];
            #pragma unroll
            for (int am = 0; am < 4; am++)
                ldsm4(ra[am][0], ra[am][1], ra[am][2], ra[am][3],
                      As + (size_t)(sb + wm * 64 + am * 16 + (lane & 15)) * LDS
                         + ks * 16 + (lane >> 4) * 8);
            #pragma unroll
            for (int bn = 0; bn < 2; bn++)
                ldsm4(rb[bn][0], rb[bn][1], rb[bn][2], rb[bn][3],
                      Bs + (size_t)(sb + wn * 32 + bn * 16 + (lane & 7)
                                    + ((lane >> 4) << 3)) * LDS
                         + ks * 16 + ((lane >> 3) & 1) * 8);
            #pragma unroll
            for (int am = 0; am < 4; am++)
                #pragma unroll
                for (int an = 0; an < 4; an++)
                    mma_f16(acc[am][an], ra[am],
                            rb[an >> 1][(an & 1) * 2], rb[an >> 1][(an & 1) * 2 + 1]);
        }
    }

    // epilogue: fp32 -> fp16 feats
    #pragma unroll
    for (int am = 0; am < 4; am++) {
        const int row = m0 + wm * 64 + am * 16 + (lane >> 2);
        #pragma unroll
        for (int an = 0; an < 4; an++) {
            const int col = n0 + wn * 32 + an * 8 + (lane & 3) * 2;
            #pragma unroll
            for (int rr = 0; rr < 2; rr++) {
                const size_t off = (size_t)(row + rr * 8) * HF + col;
                *(__half2*)(g_fhi + off) =
                    __floats2half2_rn(acc[am][an][rr * 2], acc[am][an][rr * 2 + 1]);
            }
        }
    }
}

// ---------------------------------------------------------------------------
// Kernel A2 (mma.sync + cp.async): masked softmax + P@V, d-SPLIT for 2 CTA/SM.
// blockIdx.x: bit0 = d-half, bit1 = i-tile. Each CTA: M=128 x N=128, K=208.
// P = fp16(u_j) exact-normalized; V = fp16 feats, single segment.
// ---------------------------------------------------------------------------
__global__ void __launch_bounds__(256, 2) attn_mma(const float* __restrict__ bias,
                                                   float* __restrict__ out) {
    extern __shared__ char sm[];
    __half*   Ph   = (__half*)(sm + OF_PH);     // [128][LDPH]
    __half*   Vs   = (__half*)(sm + OF_VS);     // [VSTG][16][LDV]
    __half*   uh   = (__half*)(sm + OF_UH);     // [NJP]
    float*    Sinv = (float*)(sm + OF_SI);      // [128]
    float*    red  = (float*)(sm + OF_RED);     // [32]
    unsigned* mb   = (unsigned*)(sm + OF_MB);   // [Nn*MW]

    const int tid = threadIdx.x, lane = tid & 31, warp = tid >> 5;
    const int bh = blockIdx.y, b = bh >> 3, h = bh & 7;
    const int dh = blockIdx.x & 1;              // d-half: cols [dh*128, dh*128+128)
    const int i0 = (blockIdx.x >> 1) * 128;     // i-tile
    const int wm = warp >> 2, wn = warp & 3;    // warp grid 2x4 (64i x 32d)

    const __half* fbh = g_fhi + (size_t)b * Nn * HF + h * Fout + dh * 128;

    // V stage loader: one cp16 per thread (16 rows x 128 halfs = 4096 B)
    #define AT_ISSUE(stp) do {                                                   \
        const int _st = (stp) & 3;                                               \
        const int _row = tid >> 4, _c16 = tid & 15;                              \
        const int _j = (stp) * 16 + _row;                                        \
        const int _sz = (_j < Nn) ? 16 : 0;                                      \
        const __half* _g = fbh + (size_t)(_j < Nn ? _j : 0) * HF + _c16 * 8;     \
        cp16z(Vs + (size_t)(_st * 16 + _row) * LDV + _c16 * 8, _g, _sz);         \
    } while (0)

    // prologue V loads overlap softmax/P-build below
    AT_ISSUE(0); CP_COMMIT();
    AT_ISSUE(1); CP_COMMIT();
    AT_ISSUE(2); CP_COMMIT();

    for (int i = tid; i < Nn * MW; i += 256) mb[i] = g_mbits[i];

    // softmax weights: u_j = exp(e_j - gmax), quantized to fp16
    const float* ep = g_eneigh + (size_t)bh * Nn;
    float e = (tid < Nn) ? ep[tid] : -1e30f;
    float m = e;
    #pragma unroll
    for (int o = 16; o > 0; o >>= 1) m = fmaxf(m, __shfl_xor_sync(0xffffffffu, m, o));
    if (lane == 0) red[warp] = m;
    __syncthreads();
    if (tid == 0) {
        float mm = red[0];
        for (int w = 1; w < 8; w++) mm = fmaxf(mm, red[w]);
        red[0] = mm;
    }
    __syncthreads();
    const float gmax = red[0];
    if (tid < NJP)
        uh[tid] = (tid < Nn) ? __float2half_rn(__expf(e - gmax)) : __half(0.f);
    __syncthreads();

    // build P tile (fp16, masked) + row sums from the SAME quantized values
    for (int t = tid; t < 128 * NPR; t += 256) {
        const int i = t / NPR, jp = t - i * NPR;
        const int ig = i0 + i;
        uint32_t mw_ = 0u;
        if (ig < Nn) {
            const unsigned* mrow = mb + ig * MW;
            const int j0 = jp * 2, j1 = j0 + 1;
            if ((mrow[j0 >> 5] >> (j0 & 31)) & 1u) mw_ |= 0x0000FFFFu;
            if ((mrow[j1 >> 5] >> (j1 & 31)) & 1u) mw_ |= 0xFFFF0000u;
        }
        const uint32_t uhp = ((const uint32_t*)uh)[jp];
        ((uint32_t*)(Ph + (size_t)i * LDPH))[jp] = uhp & mw_;
    }
    for (int il = warp; il < 128; il += 8) {
        const int ig = i0 + il;
        float s = 0.f;
        if (ig < Nn) {
            const unsigned* mrow = mb + ig * MW;
            for (int j = lane; j < Nn; j += 32)
                if (mrow[j >> 5] & (1u << (j & 31))) s += __half2float(uh[j]);
        }
        #pragma unroll
        for (int o = 16; o > 0; o >>= 1) s += __shfl_xor_sync(0xffffffffu, s, o);
        if (lane == 0) Sinv[il] = (ig < Nn) ? (1.f / s) : 0.f;
    }
    __syncthreads();

    // K-loop: 13 steps of k=16, 4-stage cp.async
    float acc[4][4][4];
    #pragma unroll
    for (int i = 0; i < 4; i++)
        #pragma unroll
        for (int j = 0; j < 4; j++)
            #pragma unroll
            for (int q = 0; q < 4; q++) acc[i][j][q] = 0.f;

    for (int step = 0; step < NSTEP; step++) {
        CP_WAIT2();
        __syncthreads();
        if (step + 3 < NSTEP) AT_ISSUE(step + 3);
        CP_COMMIT();

        const int kc = step * 16;
        const int vb = (step & 3) * 16;

        uint32_t ra[4][4], rb[2][4];
        #pragma unroll
        for (int am = 0; am < 4; am++)
            ldsm4(ra[am][0], ra[am][1], ra[am][2], ra[am][3],
                  Ph + (size_t)(wm * 64 + am * 16 + (lane & 15)) * LDPH
                     + kc + (lane >> 4) * 8);
        #pragma unroll
        for (int q = 0; q < 2; q++)
            ldsm4t(rb[q][0], rb[q][1], rb[q][2], rb[q][3],
                   Vs + (size_t)(vb + (lane & 15)) * LDV
                      + wn * 32 + q * 16 + ((lane >> 4) << 3));
        #pragma unroll
        for (int am = 0; am < 4; am++)
            #pragma unroll
            for (int an = 0; an < 4; an++)
                mma_f16(acc[am][an], ra[am],
                        rb[an >> 1][(an & 1) * 2], rb[an >> 1][(an & 1) * 2 + 1]);
    }

    // epilogue: scale by Sinv, add bias, store fp32
    #pragma unroll
    for (int am = 0; am < 4; am++) {
        const int il = wm * 64 + am * 16 + (lane >> 2);
        const int ig0 = i0 + il, ig1 = ig0 + 8;
        const float si0 = Sinv[il], si1 = Sinv[il + 8];
        #pragma unroll
        for (int an = 0; an < 4; an++) {
            const int d = dh * 128 + wn * 32 + an * 8 + (lane & 3) * 2;
            const float bv0 = bias[h * Fout + d];
            const float bv1 = bias[h * Fout + d + 1];
            if (ig0 < Nn) {
                float* p = out + (size_t)(b * Nn + ig0) * HF + h * Fout + d;
                *(float2*)p = make_float2(fmaf(acc[am][an][0], si0, bv0),
                                          fmaf(acc[am][an][1], si0, bv1));
            }
            if (ig1 < Nn) {
                float* p = out + (size_t)(b * Nn + ig1) * HF + h * Fout + d;
                *(float2*)p = make_float2(fmaf(acc[am][an][2], si1, bv0),
                                          fmaf(acc[am][an][3], si1, bv1));
            }
        }
    }
}

// ---------------------------------------------------------------------------
extern "C" void kernel_launch(void* const* d_in, const int* in_sizes, int n_in,
                              void* d_out, int out_size) {
    const float* X       = (const float*)d_in[0];
    const int*   A       = (const int*)  d_in[1];
    const float* W       = (const float*)d_in[2];
    // d_in[3] = a_self: no effect on output (softmax row-constant cancels)
    const float* a_neigh = (const float*)d_in[4];
    const float* bias    = (const float*)d_in[5];
    float* out = (float*)d_out;

    prep_kernel<<<64, 256>>>(W, a_neigh, A);
    eneigh_kernel<<<BN / 8, 256>>>(X);        // also writes fp16(X)
    split_w_kernel<<<HF * 64 / 256, 256>>>(W);

    cudaFuncSetAttribute(gemm1_mma, cudaFuncAttributeMaxDynamicSharedMemorySize,
                         G1_SMEM);
    cudaFuncSetAttribute(attn_mma, cudaFuncAttributeMaxDynamicSharedMemorySize,
                         ATTN_SMEM);

    gemm1_mma<<<dim3(HF / 128, BN / 128), 256, G1_SMEM>>>();
    attn_mma<<<dim3(4, Bn * Hh), 256, ATTN_SMEM>>>(bias, out);
}

// round 13
// speedup vs baseline: 1.4417x; 1.3766x over previous
#include <cuda_runtime.h>
#include <cuda_fp16.h>
#include <math.h>
#include <stdint.h>

// Problem constants
#define Bn   256
#define Nn   199
#define Fin  256
#define Hh   8
#define Fout 256
#define HF   2048          // Hh * Fout
#define BN   (Bn * Nn)     // 50944
#define MW   7             // mask words per row

// gemm1 (mma.sync) tiling — single-segment fp16: fp16(X) @ fp16(W)
#define KS   256
#define KCH  32            // K chunk per smem stage
#define NKC  (KS / KCH)    // 8
#define LDS  40            // gemm1 smem row stride (halfs): 80B, conflict-free
#define GSTG 4             // cp.async stages
#define G1_SMEM (2 * GSTG * 128 * LDS * 2)   // 81920 B

// attn (mma.sync) tiling — P precomputed fp16, V fp16; d split across CTAs
#define NJP   208          // padded j (13*16)
#define NPR   104          // j pairs
#define LDPH  216          // P smem row stride (halfs): 432B -> conflict-free
#define LDV   136          // V smem row stride (halfs): 272B -> conflict-free ldsm_t
#define NSTEP 13           // 13 k16-steps (K = 208)
#define VSTG  4

// attn smem byte offsets (all 16B aligned)
#define OF_PH 0
#define OF_VS 55296        // 128*216*2
#define OF_SI 72704        // + 4*16*136*2
#define ATTN_SMEM 73216    // + 512

// ---------------------------------------------------------------------------
// Scratch (device globals — no runtime allocation allowed)
// ---------------------------------------------------------------------------
__device__ __half        g_fhi[(size_t)BN * HF];         // feats fp16 (209 MB)
__device__ float         g_eneigh[(size_t)Bn * Hh * Nn];
__device__ float         g_wneigh[Hh * Fin];
__device__ unsigned      g_mbits[Nn * MW];
__device__ __half        g_Xs[(size_t)BN * KS];          // fp16(X) (26 MB)
__device__ __half        g_Wt[(size_t)HF * KS];          // fp16(W^T) (1 MB)
__device__ __half        g_P[(size_t)Bn * Hh * NJP * NJP]; // masked P tiles (177 MB)
__device__ float         g_Sv[(size_t)Bn * Hh * NJP];    // 1/S_i per bh (1.7 MB)

// ---------------------------------------------------------------------------
// mma.sync / ldmatrix / cp.async helpers (sm_80+, valid on plain sm_100)
// ---------------------------------------------------------------------------
__device__ __forceinline__ void ldsm4(uint32_t& r0, uint32_t& r1, uint32_t& r2,
                                      uint32_t& r3, const void* p) {
    uint32_t a = (uint32_t)__cvta_generic_to_shared(p);
    asm volatile("ldmatrix.sync.aligned.m8n8.x4.shared.b16 {%0,%1,%2,%3}, [%4];"
                 : "=r"(r0), "=r"(r1), "=r"(r2), "=r"(r3) : "r"(a));
}
__device__ __forceinline__ void ldsm4t(uint32_t& r0, uint32_t& r1, uint32_t& r2,
                                       uint32_t& r3, const void* p) {
    uint32_t a = (uint32_t)__cvta_generic_to_shared(p);
    asm volatile("ldmatrix.sync.aligned.m8n8.x4.trans.shared.b16 {%0,%1,%2,%3}, [%4];"
                 : "=r"(r0), "=r"(r1), "=r"(r2), "=r"(r3) : "r"(a));
}
__device__ __forceinline__ void mma_f16(float* c, const uint32_t* a,
                                        uint32_t b0, uint32_t b1) {
    asm volatile(
        "mma.sync.aligned.m16n8k16.row.col.f32.f16.f16.f32 "
        "{%0,%1,%2,%3}, {%4,%5,%6,%7}, {%8,%9}, {%0,%1,%2,%3};"
        : "+f"(c[0]), "+f"(c[1]), "+f"(c[2]), "+f"(c[3])
        : "r"(a[0]), "r"(a[1]), "r"(a[2]), "r"(a[3]), "r"(b0), "r"(b1));
}
__device__ __forceinline__ void cp16(void* s, const void* g) {
    uint32_t sa = (uint32_t)__cvta_generic_to_shared(s);
    asm volatile("cp.async.cg.shared.global [%0], [%1], 16;" :: "r"(sa), "l"(g));
}
__device__ __forceinline__ void cp16z(void* s, const void* g, int sz) {
    uint32_t sa = (uint32_t)__cvta_generic_to_shared(s);
    asm volatile("cp.async.cg.shared.global [%0], [%1], 16, %2;"
                 :: "r"(sa), "l"(g), "r"(sz));
}
#define CP_COMMIT() asm volatile("cp.async.commit_group;" ::: "memory")
#define CP_WAIT2()  asm volatile("cp.async.wait_group 2;" ::: "memory")

// ---------------------------------------------------------------------------
// Kernel P0: w_neigh + adjacency bitmask
// ---------------------------------------------------------------------------
__global__ void prep_kernel(const float* __restrict__ W,
                            const float* __restrict__ a_neigh,
                            const int*   __restrict__ A) {
    int t = blockIdx.x * blockDim.x + threadIdx.x;
    int stride = gridDim.x * blockDim.x;
    for (int idx = t; idx < Hh * Fin; idx += stride) {
        int h = idx / Fin, f = idx % Fin;
        const float* wp = W + ((size_t)h * Fin + f) * Fout;
        const float* ap = a_neigh + h * Fout;
        float s = 0.f;
        for (int d = 0; d < Fout; d++) s += wp[d] * ap[d];
        g_wneigh[idx] = s;
    }
    for (int idx = t; idx < Nn * MW; idx += stride) {
        int i = idx / MW, c = idx % MW;
        unsigned m = 0u;
        for (int bb = 0; bb < 32; bb++) {
            int j = c * 32 + bb;
            if (j < Nn && A[i * Nn + j] != 0) m |= (1u << bb);
        }
        g_mbits[idx] = m;
    }
}

// ---------------------------------------------------------------------------
// Kernel P1: e_neigh[b,h,n] = X[b,n,:] . w_neigh[h,:]  (fp32 exact, feeds exp)
// Fused: also writes fp16(X) to g_Xs (row already in registers).
// ---------------------------------------------------------------------------
__global__ void __launch_bounds__(256) eneigh_kernel(const float* __restrict__ X) {
    __shared__ float ws[Hh * Fin];
    const int tid = threadIdx.x;
    for (int i = tid; i < Hh * Fin; i += 256) ws[i] = g_wneigh[i];
    __syncthreads();

    const int warp = tid >> 5, lane = tid & 31;
    const int row = blockIdx.x * 8 + warp;
    const float* xp = X + (size_t)row * Fin;
    float x[8];
    #pragma unroll
    for (int k = 0; k < 8; k++) x[k] = xp[lane + 32 * k];

    #pragma unroll
    for (int k = 0; k < 8; k++)
        g_Xs[(size_t)row * KS + lane + 32 * k] = __float2half_rn(x[k]);

    const int b = row / Nn, n = row % Nn;
    #pragma unroll
    for (int h = 0; h < Hh; h++) {
        float s = 0.f;
        #pragma unroll
        for (int k = 0; k < 8; k++) s = fmaf(x[k], ws[h * Fin + lane + 32 * k], s);
        #pragma unroll
        for (int o = 16; o > 0; o >>= 1) s += __shfl_xor_sync(0xffffffffu, s, o);
        if (lane == 0) g_eneigh[(size_t)(b * Hh + h) * Nn + n] = s;
    }
}

// ---------------------------------------------------------------------------
// Kernel S1: W^T -> fp16: g_Wt[col][f] = fp16(W[h][f][d]), col = h*256+d
// ---------------------------------------------------------------------------
__global__ void __launch_bounds__(256) split_w_kernel(const float* __restrict__ W) {
    const int idx = blockIdx.x * 256 + threadIdx.x;   // < HF*64
    const int col = idx >> 6, f4 = idx & 63;
    const int h = col >> 8, d = col & 255;
    #pragma unroll
    for (int i = 0; i < 4; i++) {
        int f = f4 * 4 + i;
        float v = W[((size_t)h * Fin + f) * Fout + d];
        g_Wt[(size_t)col * KS + f] = __float2half_rn(v);
    }
}

// ---------------------------------------------------------------------------
// Kernel PB: per-bh masked softmax tile. Writes P[bh][i][j] fp16 (i<199,
// j padded to 208 with zeros) and 1/S_i. Same fp16 values / same summation
// order as the old in-attn prologue -> numerics bit-identical.
// ---------------------------------------------------------------------------
__global__ void __launch_bounds__(256) pbuild_kernel() {
    __shared__ __half    uh[NJP];
    __shared__ unsigned  mb[Nn * MW];
    __shared__ float     red[8];

    const int tid = threadIdx.x, lane = tid & 31, warp = tid >> 5;
    const int bh = blockIdx.x;

    for (int i = tid; i < Nn * MW; i += 256) mb[i] = g_mbits[i];

    const float* ep = g_eneigh + (size_t)bh * Nn;
    float e = (tid < Nn) ? ep[tid] : -1e30f;
    float m = e;
    #pragma unroll
    for (int o = 16; o > 0; o >>= 1) m = fmaxf(m, __shfl_xor_sync(0xffffffffu, m, o));
    if (lane == 0) red[warp] = m;
    __syncthreads();
    if (tid == 0) {
        float mm = red[0];
        for (int w = 1; w < 8; w++) mm = fmaxf(mm, red[w]);
        red[0] = mm;
    }
    __syncthreads();
    const float gmax = red[0];
    if (tid < NJP)
        uh[tid] = (tid < Nn) ? __float2half_rn(__expf(e - gmax)) : __half(0.f);
    __syncthreads();

    uint32_t* Pg = (uint32_t*)(g_P + (size_t)bh * NJP * NJP);
    for (int t = tid; t < Nn * NPR; t += 256) {
        const int i = t / NPR, jp = t - i * NPR;
        const unsigned* mrow = mb + i * MW;
        const int j0 = jp * 2, j1 = j0 + 1;
        uint32_t mw_ = 0u;
        if ((mrow[j0 >> 5] >> (j0 & 31)) & 1u) mw_ |= 0x0000FFFFu;
        if ((mrow[j1 >> 5] >> (j1 & 31)) & 1u) mw_ |= 0xFFFF0000u;
        Pg[i * NPR + jp] = ((const uint32_t*)uh)[jp] & mw_;
    }

    for (int il = warp; il < Nn; il += 8) {
        const unsigned* mrow = mb + il * MW;
        float s = 0.f;
        for (int j = lane; j < Nn; j += 32)
            if (mrow[j >> 5] & (1u << (j & 31))) s += __half2float(uh[j]);
        #pragma unroll
        for (int o = 16; o > 0; o >>= 1) s += __shfl_xor_sync(0xffffffffu, s, o);
        if (lane == 0) g_Sv[(size_t)bh * NJP + il] = 1.f / s;
    }
}

// ---------------------------------------------------------------------------
// Kernel G1 (mma.sync + cp.async 4-stage): feats = fp16(X) @ fp16(W'), K=256.
// Grid: (16 n-tiles, 398 m-tiles) — consecutive CTAs share the A tile in L2.
// ---------------------------------------------------------------------------
__global__ void __launch_bounds__(256, 2) gemm1_mma() {
    extern __shared__ char gsm[];
    __half* As = (__half*)gsm;                              // [GSTG*128][LDS]
    __half* Bs = (__half*)(gsm + (size_t)GSTG * 128 * LDS * 2);

    const int tid  = threadIdx.x;
    const int lane = tid & 31, warp = tid >> 5;
    const int wm = warp >> 2, wn = warp & 3;          // warp grid 2x4
    const int m0 = blockIdx.y * 128, n0 = blockIdx.x * 128;

    const __half* Ag = g_Xs + (size_t)m0 * KS;
    const __half* Bg = g_Wt + (size_t)n0 * KS;

    const int lrow0 = tid >> 2, lc16 = tid & 3;
    const int lrow1 = (tid + 256) >> 2;

    #define G1_ISSUE(c) do {                                                     \
        const int _st = (c) & 3, _ko = (c) * KCH;                                \
        cp16(As + (size_t)(_st * 128 + lrow0) * LDS + lc16 * 8,                  \
             Ag + (size_t)lrow0 * KS + _ko + lc16 * 8);                          \
        cp16(As + (size_t)(_st * 128 + lrow1) * LDS + lc16 * 8,                  \
             Ag + (size_t)lrow1 * KS + _ko + lc16 * 8);                          \
        cp16(Bs + (size_t)(_st * 128 + lrow0) * LDS + lc16 * 8,                  \
             Bg + (size_t)lrow0 * KS + _ko + lc16 * 8);                          \
        cp16(Bs + (size_t)(_st * 128 + lrow1) * LDS + lc16 * 8,                  \
             Bg + (size_t)lrow1 * KS + _ko + lc16 * 8);                          \
    } while (0)

    G1_ISSUE(0); CP_COMMIT();
    G1_ISSUE(1); CP_COMMIT();
    G1_ISSUE(2); CP_COMMIT();

    float acc[4][4][4];
    #pragma unroll
    for (int i = 0; i < 4; i++)
        #pragma unroll
        for (int j = 0; j < 4; j++)
            #pragma unroll
            for (int q = 0; q < 4; q++) acc[i][j][q] = 0.f;

    for (int c = 0; c < NKC; c++) {
        CP_WAIT2();
        __syncthreads();
        if (c + 3 < NKC) G1_ISSUE(c + 3);
        CP_COMMIT();

        const int sb = (c & 3) * 128;
        #pragma unroll
        for (int ks = 0; ks < 2; ks++) {
            uint32_t ra[4][4], rb[2][4];
            #pragma unroll
            for (int am = 0; am < 4; am++)
                ldsm4(ra[am][0], ra[am][1], ra[am][2], ra[am][3],
                      As + (size_t)(sb + wm * 64 + am * 16 + (lane & 15)) * LDS
                         + ks * 16 + (lane >> 4) * 8);
            #pragma unroll
            for (int bn = 0; bn < 2; bn++)
                ldsm4(rb[bn][0], rb[bn][1], rb[bn][2], rb[bn][3],
                      Bs + (size_t)(sb + wn * 32 + bn * 16 + (lane & 7)
                                    + ((lane >> 4) << 3)) * LDS
                         + ks * 16 + ((lane >> 3) & 1) * 8);
            #pragma unroll
            for (int am = 0; am < 4; am++)
                #pragma unroll
                for (int an = 0; an < 4; an++)
                    mma_f16(acc[am][an], ra[am],
                            rb[an >> 1][(an & 1) * 2], rb[an >> 1][(an & 1) * 2 + 1]);
        }
    }

    // epilogue: fp32 -> fp16 feats
    #pragma unroll
    for (int am = 0; am < 4; am++) {
        const int row = m0 + wm * 64 + am * 16 + (lane >> 2);
        #pragma unroll
        for (int an = 0; an < 4; an++) {
            const int col = n0 + wn * 32 + an * 8 + (lane & 3) * 2;
            #pragma unroll
            for (int rr = 0; rr < 2; rr++) {
                const size_t off = (size_t)(row + rr * 8) * HF + col;
                *(__half2*)(g_fhi + off) =
                    __floats2half2_rn(acc[am][an][rr * 2], acc[am][an][rr * 2 + 1]);
            }
        }
    }
}

// ---------------------------------------------------------------------------
// Kernel A2 (mma.sync + cp.async): P@V with precomputed P tiles.
// blockIdx.x: bit0 = d-half, bit1 = i-tile. Each CTA: M=128 x N=128, K=208.
// Prologue = cp.async of the P half-tile (group 0, committed before V groups,
// so the existing wait_group-2 discipline covers it at step 0).
// ---------------------------------------------------------------------------
__global__ void __launch_bounds__(256, 2) attn_mma(const float* __restrict__ bias,
                                                   float* __restrict__ out) {
    extern __shared__ char sm[];
    __half* Ph   = (__half*)(sm + OF_PH);     // [128][LDPH]
    __half* Vs   = (__half*)(sm + OF_VS);     // [VSTG][16][LDV]
    float*  Sinv = (float*)(sm + OF_SI);      // [128]

    const int tid = threadIdx.x, lane = tid & 31, warp = tid >> 5;
    const int bh = blockIdx.y, b = bh >> 3, h = bh & 7;
    const int dh = blockIdx.x & 1;
    const int i0 = (blockIdx.x >> 1) * 128;
    const int wm = warp >> 2, wn = warp & 3;  // warp grid 2x4 (64i x 32d)

    const __half* fbh = g_fhi + (size_t)b * Nn * HF + h * Fout + dh * 128;
    const __half* Pg  = g_P + (size_t)bh * NJP * NJP;

    // P half-tile loads: 128 rows x 208 halfs = 3328 cp16, 13 per thread.
    // Rows >= Nn are zero-filled (cp.async src-size 0).
    #pragma unroll
    for (int q = 0; q < 13; q++) {
        const int idx = tid + q * 256;
        const int row = idx / 26, c16 = idx - row * 26;
        const int ig = i0 + row;
        const int sz = (ig < Nn) ? 16 : 0;
        cp16z(Ph + (size_t)row * LDPH + c16 * 8,
              Pg + (size_t)(ig < Nn ? ig : 0) * NJP + c16 * 8, sz);
    }
    CP_COMMIT();                               // group 0 = P

    #define AT_ISSUE(stp) do {                                                   \
        const int _st = (stp) & 3;                                               \
        const int _row = tid >> 4, _c16 = tid & 15;                              \
        const int _j = (stp) * 16 + _row;                                        \
        const int _sz = (_j < Nn) ? 16 : 0;                                      \
        const __half* _g = fbh + (size_t)(_j < Nn ? _j : 0) * HF + _c16 * 8;     \
        cp16z(Vs + (size_t)(_st * 16 + _row) * LDV + _c16 * 8, _g, _sz);         \
    } while (0)

    AT_ISSUE(0); CP_COMMIT();
    AT_ISSUE(1); CP_COMMIT();
    AT_ISSUE(2); CP_COMMIT();

    // Sinv gather (plain LDG; ordered before use by the loop's __syncthreads)
    if (tid < 128) {
        const int ig = i0 + tid;
        Sinv[tid] = (ig < Nn) ? g_Sv[(size_t)bh * NJP + ig] : 0.f;
    }

    float acc[4][4][4];
    #pragma unroll
    for (int i = 0; i < 4; i++)
        #pragma unroll
        for (int j = 0; j < 4; j++)
            #pragma unroll
            for (int q = 0; q < 4; q++) acc[i][j][q] = 0.f;

    for (int step = 0; step < NSTEP; step++) {
        CP_WAIT2();
        __syncthreads();
        if (step + 3 < NSTEP) AT_ISSUE(step + 3);
        CP_COMMIT();

        const int kc = step * 16;
        const int vb = (step & 3) * 16;

        uint32_t ra[4][4], rb[2][4];
        #pragma unroll
        for (int am = 0; am < 4; am++)
            ldsm4(ra[am][0], ra[am][1], ra[am][2], ra[am][3],
                  Ph + (size_t)(wm * 64 + am * 16 + (lane & 15)) * LDPH
                     + kc + (lane >> 4) * 8);
        #pragma unroll
        for (int q = 0; q < 2; q++)
            ldsm4t(rb[q][0], rb[q][1], rb[q][2], rb[q][3],
                   Vs + (size_t)(vb + (lane & 15)) * LDV
                      + wn * 32 + q * 16 + ((lane >> 4) << 3));
        #pragma unroll
        for (int am = 0; am < 4; am++)
            #pragma unroll
            for (int an = 0; an < 4; an++)
                mma_f16(acc[am][an], ra[am],
                        rb[an >> 1][(an & 1) * 2], rb[an >> 1][(an & 1) * 2 + 1]);
    }

    // epilogue: scale by Sinv, add bias, store fp32
    #pragma unroll
    for (int am = 0; am < 4; am++) {
        const int il = wm * 64 + am * 16 + (lane >> 2);
        const int ig0 = i0 + il, ig1 = ig0 + 8;
        const float si0 = Sinv[il], si1 = Sinv[il + 8];
        #pragma unroll
        for (int an = 0; an < 4; an++) {
            const int d = dh * 128 + wn * 32 + an * 8 + (lane & 3) * 2;
            const float bv0 = bias[h * Fout + d];
            const float bv1 = bias[h * Fout + d + 1];
            if (ig0 < Nn) {
                float* p = out + (size_t)(b * Nn + ig0) * HF + h * Fout + d;
                *(float2*)p = make_float2(fmaf(acc[am][an][0], si0, bv0),
                                          fmaf(acc[am][an][1], si0, bv1));
            }
            if (ig1 < Nn) {
                float* p = out + (size_t)(b * Nn + ig1) * HF + h * Fout + d;
                *(float2*)p = make_float2(fmaf(acc[am][an][2], si1, bv0),
                                          fmaf(acc[am][an][3], si1, bv1));
            }
        }
    }
}

// ---------------------------------------------------------------------------
extern "C" void kernel_launch(void* const* d_in, const int* in_sizes, int n_in,
                              void* d_out, int out_size) {
    const float* X       = (const float*)d_in[0];
    const int*   A       = (const int*)  d_in[1];
    const float* W       = (const float*)d_in[2];
    // d_in[3] = a_self: no effect on output (softmax row-constant cancels)
    const float* a_neigh = (const float*)d_in[4];
    const float* bias    = (const float*)d_in[5];
    float* out = (float*)d_out;

    prep_kernel<<<64, 256>>>(W, a_neigh, A);
    eneigh_kernel<<<BN / 8, 256>>>(X);        // also writes fp16(X)
    split_w_kernel<<<HF * 64 / 256, 256>>>(W);
    pbuild_kernel<<<Bn * Hh, 256>>>();        // masked softmax P tiles + 1/S

    cudaFuncSetAttribute(gemm1_mma, cudaFuncAttributeMaxDynamicSharedMemorySize,
                         G1_SMEM);
    cudaFuncSetAttribute(attn_mma, cudaFuncAttributeMaxDynamicSharedMemorySize,
                         ATTN_SMEM);

    gemm1_mma<<<dim3(HF / 128, BN / 128), 256, G1_SMEM>>>();
    attn_mma<<<dim3(4, Bn * Hh), 256, ATTN_SMEM>>>(bias, out);
}

// round 17
// speedup vs baseline: 1.5207x; 1.0548x over previous
#include <cuda_runtime.h>
#include <cuda_fp16.h>
#include <math.h>
#include <stdint.h>

// Problem constants
#define Bn   256
#define Nn   199
#define Fin  256
#define Hh   8
#define Fout 256
#define HF   2048          // Hh * Fout
#define BN   (Bn * Nn)     // 50944

// gemm1 (mma.sync) tiling — fp16, B smem-resident, A double-buffered
#define KS    256
#define KCH2  64           // A chunk (K halfs per stage)
#define NKC2  (KS / KCH2)  // 4
#define LDA2  72           // A smem row stride (halfs): 144B -> conflict-free
#define LDB2  264          // B smem row stride (halfs): 528B -> conflict-free
#define G1_B_BYTES (128 * LDB2 * 2)                  // 67584
#define G1_SMEM (G1_B_BYTES + 2 * 128 * LDA2 * 2)    // 104448 (2 CTA/SM)

// attn (mma.sync) tiling — P precomputed fp16, V fp16; d split across CTAs
#define NJP   208          // padded j (13*16)
#define NPR   104          // j pairs
#define LDPH  216          // P smem row stride (halfs)
#define LDV   136          // V smem row stride (halfs)
#define NSTEP 13           // 13 k16-steps (K = 208)
#define VSTG  4

// attn smem byte offsets (all 16B aligned)
#define OF_PH 0
#define OF_VS 55296        // 128*216*2
#define OF_SI 72704        // + 4*16*136*2
#define ATTN_SMEM 73216    // + 512

// ---------------------------------------------------------------------------
// Scratch (device globals — no runtime allocation allowed)
// ---------------------------------------------------------------------------
__device__ __half        g_fhi[(size_t)BN * HF];         // feats fp16 (209 MB)
__device__ float         g_eneigh[(size_t)Bn * Hh * Nn];
__device__ float         g_wneigh[Hh * Fin];
__device__ uint32_t      g_m32[Nn * NPR];                // expanded pair masks (83 KB)
__device__ __half        g_Xs[(size_t)BN * KS];          // fp16(X) (26 MB)
__device__ __half        g_Wt[(size_t)HF * KS];          // fp16(W^T) (1 MB)
__device__ __half        g_P[(size_t)Bn * Hh * NJP * NJP]; // masked P tiles (177 MB)
__device__ float         g_Sv[(size_t)Bn * Hh * NJP];    // 1/S_i per bh (1.7 MB)

// ---------------------------------------------------------------------------
// mma.sync / ldmatrix / cp.async helpers (sm_80+, valid on plain sm_100)
// ---------------------------------------------------------------------------
__device__ __forceinline__ void ldsm4(uint32_t& r0, uint32_t& r1, uint32_t& r2,
                                      uint32_t& r3, const void* p) {
    uint32_t a = (uint32_t)__cvta_generic_to_shared(p);
    asm volatile("ldmatrix.sync.aligned.m8n8.x4.shared.b16 {%0,%1,%2,%3}, [%4];"
                 : "=r"(r0), "=r"(r1), "=r"(r2), "=r"(r3) : "r"(a));
}
__device__ __forceinline__ void ldsm4t(uint32_t& r0, uint32_t& r1, uint32_t& r2,
                                       uint32_t& r3, const void* p) {
    uint32_t a = (uint32_t)__cvta_generic_to_shared(p);
    asm volatile("ldmatrix.sync.aligned.m8n8.x4.trans.shared.b16 {%0,%1,%2,%3}, [%4];"
                 : "=r"(r0), "=r"(r1), "=r"(r2), "=r"(r3) : "r"(a));
}
__device__ __forceinline__ void mma_f16(float* c, const uint32_t* a,
                                        uint32_t b0, uint32_t b1) {
    asm volatile(
        "mma.sync.aligned.m16n8k16.row.col.f32.f16.f16.f32 "
        "{%0,%1,%2,%3}, {%4,%5,%6,%7}, {%8,%9}, {%0,%1,%2,%3};"
        : "+f"(c[0]), "+f"(c[1]), "+f"(c[2]), "+f"(c[3])
        : "r"(a[0]), "r"(a[1]), "r"(a[2]), "r"(a[3]), "r"(b0), "r"(b1));
}
__device__ __forceinline__ void cp16(void* s, const void* g) {
    uint32_t sa = (uint32_t)__cvta_generic_to_shared(s);
    asm volatile("cp.async.cg.shared.global [%0], [%1], 16;" :: "r"(sa), "l"(g));
}
__device__ __forceinline__ void cp16z(void* s, const void* g, int sz) {
    uint32_t sa = (uint32_t)__cvta_generic_to_shared(s);
    asm volatile("cp.async.cg.shared.global [%0], [%1], 16, %2;"
                 :: "r"(sa), "l"(g), "r"(sz));
}
#define CP_COMMIT() asm volatile("cp.async.commit_group;" ::: "memory")
#define CP_WAIT0()  asm volatile("cp.async.wait_group 0;" ::: "memory")
#define CP_WAIT2()  asm volatile("cp.async.wait_group 2;" ::: "memory")

// ---------------------------------------------------------------------------
// Kernel P0: w_neigh + expanded pair-mask g_m32
// ---------------------------------------------------------------------------
__global__ void prep_kernel(const float* __restrict__ W,
                            const float* __restrict__ a_neigh,
                            const int*   __restrict__ A) {
    int t = blockIdx.x * blockDim.x + threadIdx.x;
    int stride = gridDim.x * blockDim.x;
    for (int idx = t; idx < Hh * Fin; idx += stride) {
        int h = idx / Fin, f = idx % Fin;
        const float* wp = W + ((size_t)h * Fin + f) * Fout;
        const float* ap = a_neigh + h * Fout;
        float s = 0.f;
        for (int d = 0; d < Fout; d++) s += wp[d] * ap[d];
        g_wneigh[idx] = s;
    }
    for (int idx = t; idx < Nn * NPR; idx += stride) {
        int i = idx / NPR, jp = idx - i * NPR;
        int j0 = jp * 2, j1 = j0 + 1;
        uint32_t m = 0u;
        if (j0 < Nn && A[i * Nn + j0] != 0) m |= 0x0000FFFFu;
        if (j1 < Nn && A[i * Nn + j1] != 0) m |= 0xFFFF0000u;
        g_m32[idx] = m;
    }
}

// ---------------------------------------------------------------------------
// Kernel P1: e_neigh[b,h,n] = X[b,n,:] . w_neigh[h,:]  (fp32 exact, feeds exp)
// Fused: also writes fp16(X) to g_Xs (row already in registers).
// ---------------------------------------------------------------------------
__global__ void __launch_bounds__(256) eneigh_kernel(const float* __restrict__ X) {
    __shared__ float ws[Hh * Fin];
    const int tid = threadIdx.x;
    for (int i = tid; i < Hh * Fin; i += 256) ws[i] = g_wneigh[i];
    __syncthreads();

    const int warp = tid >> 5, lane = tid & 31;
    const int row = blockIdx.x * 8 + warp;
    const float* xp = X + (size_t)row * Fin;
    float x[8];
    #pragma unroll
    for (int k = 0; k < 8; k++) x[k] = xp[lane + 32 * k];

    #pragma unroll
    for (int k = 0; k < 8; k++)
        g_Xs[(size_t)row * KS + lane + 32 * k] = __float2half_rn(x[k]);

    const int b = row / Nn, n = row % Nn;
    #pragma unroll
    for (int h = 0; h < Hh; h++) {
        float s = 0.f;
        #pragma unroll
        for (int k = 0; k < 8; k++) s = fmaf(x[k], ws[h * Fin + lane + 32 * k], s);
        #pragma unroll
        for (int o = 16; o > 0; o >>= 1) s += __shfl_xor_sync(0xffffffffu, s, o);
        if (lane == 0) g_eneigh[(size_t)(b * Hh + h) * Nn + n] = s;
    }
}

// ---------------------------------------------------------------------------
// Kernel S1: W^T -> fp16: g_Wt[col][f] = fp16(W[h][f][d]), col = h*256+d
// ---------------------------------------------------------------------------
__global__ void __launch_bounds__(256) split_w_kernel(const float* __restrict__ W) {
    const int idx = blockIdx.x * 256 + threadIdx.x;   // < HF*64
    const int col = idx >> 6, f4 = idx & 63;
    const int h = col >> 8, d = col & 255;
    #pragma unroll
    for (int i = 0; i < 4; i++) {
        int f = f4 * 4 + i;
        float v = W[((size_t)h * Fin + f) * Fout + d];
        g_Wt[(size_t)col * KS + f] = __float2half_rn(v);
    }
}

// ---------------------------------------------------------------------------
// Kernel PB: per-bh masked softmax tile. One pass: P word = m32 & u-pair,
// row sum accumulated from the SAME masked fp16 values (masked lanes add 0).
// Warp-per-row; no division, no bitmask staging.
// ---------------------------------------------------------------------------
__global__ void __launch_bounds__(256) pbuild_kernel() {
    __shared__ __align__(16) __half uh[NJP];
    __shared__ float red[8];

    const int tid = threadIdx.x, lane = tid & 31, warp = tid >> 5;
    const int bh = blockIdx.x;

    const float* ep = g_eneigh + (size_t)bh * Nn;
    float e = (tid < Nn) ? ep[tid] : -1e30f;
    float m = e;
    #pragma unroll
    for (int o = 16; o > 0; o >>= 1) m = fmaxf(m, __shfl_xor_sync(0xffffffffu, m, o));
    if (lane == 0) red[warp] = m;
    __syncthreads();
    if (tid == 0) {
        float mm = red[0];
        for (int w = 1; w < 8; w++) mm = fmaxf(mm, red[w]);
        red[0] = mm;
    }
    __syncthreads();
    const float gmax = red[0];
    if (tid < NJP)
        uh[tid] = (tid < Nn) ? __float2half_rn(__expf(e - gmax)) : __half(0.f);
    __syncthreads();

    const uint32_t* uh32 = (const uint32_t*)uh;
    uint32_t* Pg = (uint32_t*)(g_P + (size_t)bh * NJP * NJP);
    for (int i = warp; i < Nn; i += 8) {
        const uint32_t* mrow = g_m32 + i * NPR;
        uint32_t* prow = Pg + i * NPR;
        float s = 0.f;
        for (int jp = lane; jp < NPR; jp += 32) {
            const uint32_t w = mrow[jp] & uh32[jp];
            prow[jp] = w;
            const __half2 hv = *(const __half2*)&w;
            s += __half2float(hv.x) + __half2float(hv.y);
        }
        #pragma unroll
        for (int o = 16; o > 0; o >>= 1) s += __shfl_xor_sync(0xffffffffu, s, o);
        if (lane == 0) g_Sv[(size_t)bh * NJP + i] = 1.f / s;
    }
}

// ---------------------------------------------------------------------------
// Kernel G1 (mma.sync): feats = fp16(X) @ fp16(W'), K=256.
// B tile (128 x 256) loaded ONCE into smem; A double-buffered in 64-K chunks.
// Grid: (16 n-tiles, 398 m-tiles) — consecutive CTAs share the A tile in L2.
// ---------------------------------------------------------------------------
__global__ void __launch_bounds__(256, 2) gemm1_mma() {
    extern __shared__ char gsm[];
    __half* Bs = (__half*)gsm;                        // [128][LDB2]
    __half* As = (__half*)(gsm + G1_B_BYTES);         // [2][128][LDA2]

    const int tid  = threadIdx.x;
    const int lane = tid & 31, warp = tid >> 5;
    const int wm = warp >> 2, wn = warp & 3;          // warp grid 2x4
    const int m0 = blockIdx.y * 128, n0 = blockIdx.x * 128;

    const __half* Ag = g_Xs + (size_t)m0 * KS;
    const __half* Bg = g_Wt + (size_t)n0 * KS;

    // A chunk loader: 128 rows x 64 halfs = 128 x 8 vec16 = 1024, 4 per thread
    #define G1_ISSUE_A(c) do {                                                   \
        const int _sb = ((c) & 1) * 128, _ko = (c) * KCH2;                       \
        _Pragma("unroll")                                                        \
        for (int _q = 0; _q < 4; _q++) {                                         \
            const int _idx = _q * 256 + tid;          /* < 1024 */               \
            const int _row = _idx >> 3, _c16 = _idx & 7;  /* row<128, c16<8 */   \
            cp16(As + (size_t)(_sb + _row) * LDA2 + _c16 * 8,                    \
                 Ag + (size_t)_row * KS + _ko + _c16 * 8);                       \
        }                                                                        \
    } while (0)

    // B load (once): 128 rows x 256 halfs = 128 x 32 vec16 = 4096, 16/thread
    #pragma unroll
    for (int q = 0; q < 16; q++) {
        const int idx = q * 256 + tid;                // < 4096
        const int row = idx >> 5, c32 = idx & 31;     // row < 128, c32 < 32
        cp16(Bs + (size_t)row * LDB2 + c32 * 8, Bg + (size_t)row * KS + c32 * 8);
    }
    G1_ISSUE_A(0);
    CP_COMMIT();

    float acc[4][4][4];
    #pragma unroll
    for (int i = 0; i < 4; i++)
        #pragma unroll
        for (int j = 0; j < 4; j++)
            #pragma unroll
            for (int q = 0; q < 4; q++) acc[i][j][q] = 0.f;

    for (int c = 0; c < NKC2; c++) {
        CP_WAIT0();               // A(c) (+B on c=0) landed in this thread
        __syncthreads();          // all warps done with compute(c-1); stage free
        if (c + 1 < NKC2) G1_ISSUE_A(c + 1);
        CP_COMMIT();              // uniform group count

        const int ab = (c & 1) * 128;
        const int kc = c * KCH2;
        #pragma unroll
        for (int ks = 0; ks < 4; ks++) {
            uint32_t ra[4][4], rb[2][4];
            #pragma unroll
            for (int am = 0; am < 4; am++)
                ldsm4(ra[am][0], ra[am][1], ra[am][2], ra[am][3],
                      As + (size_t)(ab + wm * 64 + am * 16 + (lane & 15)) * LDA2
                         + ks * 16 + (lane >> 4) * 8);
            #pragma unroll
            for (int bn = 0; bn < 2; bn++)
                ldsm4(rb[bn][0], rb[bn][1], rb[bn][2], rb[bn][3],
                      Bs + (size_t)(wn * 32 + bn * 16 + (lane & 7)
                                    + ((lane >> 4) << 3)) * LDB2
                         + kc + ks * 16 + ((lane >> 3) & 1) * 8);
            #pragma unroll
            for (int am = 0; am < 4; am++)
                #pragma unroll
                for (int an = 0; an < 4; an++)
                    mma_f16(acc[am][an], ra[am],
                            rb[an >> 1][(an & 1) * 2], rb[an >> 1][(an & 1) * 2 + 1]);
        }
    }

    // epilogue: fp32 -> fp16 feats
    #pragma unroll
    for (int am = 0; am < 4; am++) {
        const int row = m0 + wm * 64 + am * 16 + (lane >> 2);
        #pragma unroll
        for (int an = 0; an < 4; an++) {
            const int col = n0 + wn * 32 + an * 8 + (lane & 3) * 2;
            #pragma unroll
            for (int rr = 0; rr < 2; rr++) {
                const size_t off = (size_t)(row + rr * 8) * HF + col;
                *(__half2*)(g_fhi + off) =
                    __floats2half2_rn(acc[am][an][rr * 2], acc[am][an][rr * 2 + 1]);
            }
        }
    }
}

// ---------------------------------------------------------------------------
// Kernel A2 (mma.sync + cp.async): P@V with precomputed P tiles (unchanged).
// ---------------------------------------------------------------------------
__global__ void __launch_bounds__(256, 2) attn_mma(const float* __restrict__ bias,
                                                   float* __restrict__ out) {
    extern __shared__ char sm[];
    __half* Ph   = (__half*)(sm + OF_PH);     // [128][LDPH]
    __half* Vs   = (__half*)(sm + OF_VS);     // [VSTG][16][LDV]
    float*  Sinv = (float*)(sm + OF_SI);      // [128]

    const int tid = threadIdx.x, lane = tid & 31, warp = tid >> 5;
    const int bh = blockIdx.y, b = bh >> 3, h = bh & 7;
    const int dh = blockIdx.x & 1;
    const int i0 = (blockIdx.x >> 1) * 128;
    const int wm = warp >> 2, wn = warp & 3;  // warp grid 2x4 (64i x 32d)

    const __half* fbh = g_fhi + (size_t)b * Nn * HF + h * Fout + dh * 128;
    const __half* Pg  = g_P + (size_t)bh * NJP * NJP;

    #pragma unroll
    for (int q = 0; q < 13; q++) {
        const int idx = tid + q * 256;
        const int row = idx / 26, c16 = idx - row * 26;
        const int ig = i0 + row;
        const int sz = (ig < Nn) ? 16 : 0;
        cp16z(Ph + (size_t)row * LDPH + c16 * 8,
              Pg + (size_t)(ig < Nn ? ig : 0) * NJP + c16 * 8, sz);
    }
    CP_COMMIT();                               // group 0 = P

    #define AT_ISSUE(stp) do {                                                   \
        const int _st = (stp) & 3;                                               \
        const int _row = tid >> 4, _c16 = tid & 15;                              \
        const int _j = (stp) * 16 + _row;                                        \
        const int _sz = (_j < Nn) ? 16 : 0;                                      \
        const __half* _g = fbh + (size_t)(_j < Nn ? _j : 0) * HF + _c16 * 8;     \
        cp16z(Vs + (size_t)(_st * 16 + _row) * LDV + _c16 * 8, _g, _sz);         \
    } while (0)

    AT_ISSUE(0); CP_COMMIT();
    AT_ISSUE(1); CP_COMMIT();
    AT_ISSUE(2); CP_COMMIT();

    if (tid < 128) {
        const int ig = i0 + tid;
        Sinv[tid] = (ig < Nn) ? g_Sv[(size_t)bh * NJP + ig] : 0.f;
    }

    float acc[4][4][4];
    #pragma unroll
    for (int i = 0; i < 4; i++)
        #pragma unroll
        for (int j = 0; j < 4; j++)
            #pragma unroll
            for (int q = 0; q < 4; q++) acc[i][j][q] = 0.f;

    for (int step = 0; step < NSTEP; step++) {
        CP_WAIT2();
        __syncthreads();
        if (step + 3 < NSTEP) AT_ISSUE(step + 3);
        CP_COMMIT();

        const int kc = step * 16;
        const int vb = (step & 3) * 16;

        uint32_t ra[4][4], rb[2][4];
        #pragma unroll
        for (int am = 0; am < 4; am++)
            ldsm4(ra[am][0], ra[am][1], ra[am][2], ra[am][3],
                  Ph + (size_t)(wm * 64 + am * 16 + (lane & 15)) * LDPH
                     + kc + (lane >> 4) * 8);
        #pragma unroll
        for (int q = 0; q < 2; q++)
            ldsm4t(rb[q][0], rb[q][1], rb[q][2], rb[q][3],
                   Vs + (size_t)(vb + (lane & 15)) * LDV
                      + wn * 32 + q * 16 + ((lane >> 4) << 3));
        #pragma unroll
        for (int am = 0; am < 4; am++)
            #pragma unroll
            for (int an = 0; an < 4; an++)
                mma_f16(acc[am][an], ra[am],
                        rb[an >> 1][(an & 1) * 2], rb[an >> 1][(an & 1) * 2 + 1]);
    }

    #pragma unroll
    for (int am = 0; am < 4; am++) {
        const int il = wm * 64 + am * 16 + (lane >> 2);
        const int ig0 = i0 + il, ig1 = ig0 + 8;
        const float si0 = Sinv[il], si1 = Sinv[il + 8];
        #pragma unroll
        for (int an = 0; an < 4; an++) {
            const int d = dh * 128 + wn * 32 + an * 8 + (lane & 3) * 2;
            const float bv0 = bias[h * Fout + d];
            const float bv1 = bias[h * Fout + d + 1];
            if (ig0 < Nn) {
                float* p = out + (size_t)(b * Nn + ig0) * HF + h * Fout + d;
                *(float2*)p = make_float2(fmaf(acc[am][an][0], si0, bv0),
                                          fmaf(acc[am][an][1], si0, bv1));
            }
            if (ig1 < Nn) {
                float* p = out + (size_t)(b * Nn + ig1) * HF + h * Fout + d;
                *(float2*)p = make_float2(fmaf(acc[am][an][2], si1, bv0),
                                          fmaf(acc[am][an][3], si1, bv1));
            }
        }
    }
}

// ---------------------------------------------------------------------------
extern "C" void kernel_launch(void* const* d_in, const int* in_sizes, int n_in,
                              void* d_out, int out_size) {
    const float* X       = (const float*)d_in[0];
    const int*   A       = (const int*)  d_in[1];
    const float* W       = (const float*)d_in[2];
    // d_in[3] = a_self: no effect on output (softmax row-constant cancels)
    const float* a_neigh = (const float*)d_in[4];
    const float* bias    = (const float*)d_in[5];
    float* out = (float*)d_out;

    prep_kernel<<<64, 256>>>(W, a_neigh, A);
    eneigh_kernel<<<BN / 8, 256>>>(X);        // also writes fp16(X)
    split_w_kernel<<<HF * 64 / 256, 256>>>(W);
    pbuild_kernel<<<Bn * Hh, 256>>>();        // masked softmax P tiles + 1/S

    cudaFuncSetAttribute(gemm1_mma, cudaFuncAttributeMaxDynamicSharedMemorySize,
                         G1_SMEM);
    cudaFuncSetAttribute(attn_mma, cudaFuncAttributeMaxDynamicSharedMemorySize,
                         ATTN_SMEM);

    gemm1_mma<<<dim3(HF / 128, BN / 128), 256, G1_SMEM>>>();
    attn_mma<<<dim3(4, Bn * Hh), 256, ATTN_SMEM>>>(bias, out);
}